// round 7
// baseline (speedup 1.0000x reference)
#include <cuda_runtime.h>
#include <cstdint>
#include <math.h>

#define BDIM 2
#define TLEN 2048
#define CDIM 1024
#define NH   16
#define DH   64
#define MROWS (BDIM * TLEN)   // 4096

// Scratch (allocation-free rule: __device__ globals)
__device__ float g_q[(size_t)BDIM * NH * TLEN * DH];
__device__ float g_k[(size_t)BDIM * NH * TLEN * DH];
__device__ float g_v[(size_t)BDIM * NH * TLEN * DH];
__device__ float g_att[(size_t)MROWS * CDIM];   // [B,T,C] layout

// ============================================================================
// helpers
// ============================================================================
__device__ __forceinline__ float f2tf32f(float f) {
    uint32_t r;
    asm("cvt.rna.tf32.f32 %0, %1;" : "=r"(r) : "f"(f));
    return __uint_as_float(r);
}
__device__ __forceinline__ float4 cvt4(float4 v) {
    return make_float4(f2tf32f(v.x), f2tf32f(v.y), f2tf32f(v.z), f2tf32f(v.w));
}
__device__ __forceinline__ void mma_tf32(float* d, const uint32_t* a,
                                         const uint32_t* b) {
    asm volatile(
        "mma.sync.aligned.m16n8k8.row.col.f32.tf32.tf32.f32 "
        "{%0,%1,%2,%3}, {%4,%5,%6,%7}, {%8,%9}, {%0,%1,%2,%3};"
        : "+f"(d[0]), "+f"(d[1]), "+f"(d[2]), "+f"(d[3])
        : "r"(a[0]), "r"(a[1]), "r"(a[2]), "r"(a[3]), "r"(b[0]), "r"(b[1]));
}

// ============================================================================
// tf32 mma.sync GEMM (unchanged from round 4/6)
// ============================================================================
#define BK  16
#define LDT 20
template <int SCATTER>
__global__ void __launch_bounds__(256, 2) gemm_mma_kernel(
    const float* __restrict__ A,
    const float* __restrict__ W0,
    const float* __restrict__ W1,
    const float* __restrict__ W2,
    float* __restrict__ Cout)
{
    const int K = CDIM;
    __shared__ float As[2][128][LDT];
    __shared__ float Ws[2][128][LDT];

    const float* W;
    float* dst;
    if (SCATTER) {
        int z = blockIdx.z;
        W   = (z == 0) ? W0  : (z == 1) ? W1  : W2;
        dst = (z == 0) ? g_q : (z == 1) ? g_k : g_v;
    } else {
        W   = W0;
        dst = Cout;
    }
    const float* Ap = SCATTER ? A : g_att;

    const int bm0  = blockIdx.y * 128;
    const int bn0  = blockIdx.x * 128;
    const int tid  = threadIdx.x;
    const int lane = tid & 31;
    const int wid  = tid >> 5;
    const int g    = lane >> 2;
    const int tig  = lane & 3;
    const int wm   = (wid & 3) * 32;
    const int wn   = (wid >> 2) * 64;

    const int r0 = tid >> 2;
    const int c4 = (tid & 3) * 4;
    const int r1 = r0 + 64;

    float d[2][8][4];
#pragma unroll
    for (int mc = 0; mc < 2; mc++)
#pragma unroll
        for (int nc = 0; nc < 8; nc++)
#pragma unroll
            for (int v = 0; v < 4; v++) d[mc][nc][v] = 0.f;

    float4 pa0, pa1, pw0, pw1;
    pa0 = *(const float4*)&Ap[(size_t)(bm0 + r0) * K + c4];
    pa1 = *(const float4*)&Ap[(size_t)(bm0 + r1) * K + c4];
    pw0 = *(const float4*)&W [(size_t)(bn0 + r0) * K + c4];
    pw1 = *(const float4*)&W [(size_t)(bn0 + r1) * K + c4];
    *(float4*)&As[0][r0][c4] = cvt4(pa0);
    *(float4*)&As[0][r1][c4] = cvt4(pa1);
    *(float4*)&Ws[0][r0][c4] = cvt4(pw0);
    *(float4*)&Ws[0][r1][c4] = cvt4(pw1);
    __syncthreads();

    int buf = 0;
    for (int k0 = BK; k0 <= K; k0 += BK) {
        const bool more = (k0 < K);
        if (more) {
            pa0 = *(const float4*)&Ap[(size_t)(bm0 + r0) * K + k0 + c4];
            pa1 = *(const float4*)&Ap[(size_t)(bm0 + r1) * K + k0 + c4];
            pw0 = *(const float4*)&W [(size_t)(bn0 + r0) * K + k0 + c4];
            pw1 = *(const float4*)&W [(size_t)(bn0 + r1) * K + k0 + c4];
        }
#pragma unroll
        for (int kk = 0; kk < BK; kk += 8) {
            uint32_t a[2][4];
#pragma unroll
            for (int mc = 0; mc < 2; mc++) {
                int row = wm + mc * 16 + g;
                a[mc][0] = __float_as_uint(As[buf][row    ][kk + tig]);
                a[mc][1] = __float_as_uint(As[buf][row + 8][kk + tig]);
                a[mc][2] = __float_as_uint(As[buf][row    ][kk + tig + 4]);
                a[mc][3] = __float_as_uint(As[buf][row + 8][kk + tig + 4]);
            }
#pragma unroll
            for (int nc = 0; nc < 8; nc++) {
                uint32_t b[2];
                int row = wn + nc * 8 + g;
                b[0] = __float_as_uint(Ws[buf][row][kk + tig]);
                b[1] = __float_as_uint(Ws[buf][row][kk + tig + 4]);
                mma_tf32(d[0][nc], a[0], b);
                mma_tf32(d[1][nc], a[1], b);
            }
        }
        if (more) {
            const int nb = buf ^ 1;
            *(float4*)&As[nb][r0][c4] = cvt4(pa0);
            *(float4*)&As[nb][r1][c4] = cvt4(pa1);
            *(float4*)&Ws[nb][r0][c4] = cvt4(pw0);
            *(float4*)&Ws[nb][r1][c4] = cvt4(pw1);
            __syncthreads();
            buf = nb;
        }
    }

#pragma unroll
    for (int mc = 0; mc < 2; mc++) {
#pragma unroll
        for (int nc = 0; nc < 8; nc++) {
            int n = bn0 + wn + nc * 8 + tig * 2;
#pragma unroll
            for (int rr = 0; rr < 2; rr++) {
                int m = bm0 + wm + mc * 16 + g + rr * 8;
                float2 val = make_float2(d[mc][nc][rr * 2 + 0], d[mc][nc][rr * 2 + 1]);
                if (SCATTER) {
                    int bb = m >> 11;
                    int tt = m & 2047;
                    int hh = n >> 6;
                    int dd = n & 63;
                    *(float2*)&dst[(((size_t)bb * NH + hh) * TLEN + tt) * DH + dd] = val;
                } else {
                    *(float2*)&dst[(size_t)m * CDIM + n] = val;
                }
            }
        }
    }
}

// ============================================================================
// tf32 mma.sync causal flash attention, v2.
// CTA = 256 q rows, 512 threads = 16 warps x 16 rows (warp-local softmax).
// K/V tiles double-buffered in smem with register prefetch (one sync per kt).
// 1 CTA/SM (206KB smem). grid = (T/256, B*H), big q-tiles first.
// ============================================================================
#define LDQ 68
#define LDK 68
#define LDV 72
#define LDP 68
#define QROWS2 256
// floats: qs 256*68=17408, ks 2*64*68=8704, vs 2*64*72=9216, ps 16*16*68=17408
#define ATT2_SMEM ((17408 + 8704 + 9216 + 17408) * 4)   // 210944 B

__global__ void __launch_bounds__(512, 1) attn_mma2_kernel()
{
    extern __shared__ float sm[];
    float* qs  = sm;                        // [256][LDQ]
    float* ksb = qs + QROWS2 * LDQ;         // [2][64][LDK]
    float* vsb = ksb + 2 * 64 * LDK;        // [2][64][LDV]
    float* psa = vsb + 2 * 64 * LDV;        // [16][16][LDP]

    const int qt = (gridDim.x - 1) - blockIdx.x;   // big tiles first
    const int bh = blockIdx.y;
    const float* qg = g_q + (size_t)bh * TLEN * DH;
    const float* kg = g_k + (size_t)bh * TLEN * DH;
    const float* vg = g_v + (size_t)bh * TLEN * DH;

    const int tid  = threadIdx.x;
    const int lane = tid & 31;
    const int wid  = tid >> 5;              // 0..15
    const int g    = lane >> 2;
    const int tig  = lane & 3;
    float* ps = psa + wid * 16 * LDP;

    // stage Q tile (scaled, tf32): 256 rows x 16 float4 = 4096, 8 per thread
#pragma unroll
    for (int l = 0; l < 8; l++) {
        int idx = tid + l * 512;
        int r   = idx >> 4;                 // 0..255
        int c4  = (idx & 15) * 4;
        float4 v = *(const float4*)&qg[(size_t)(qt * QROWS2 + r) * DH + c4];
        float4 t = make_float4(f2tf32f(v.x * 0.125f), f2tf32f(v.y * 0.125f),
                               f2tf32f(v.z * 0.125f), f2tf32f(v.w * 0.125f));
        *(float4*)&qs[r * LDQ + c4] = t;
    }

    // initial K/V tile (kt=0) into buffer 0: 1024 float4 each, 2 per thread
#pragma unroll
    for (int l = 0; l < 2; l++) {
        int idx = tid + l * 512;            // 0..1023
        int r   = idx >> 4;                 // 0..63
        int c4  = (idx & 15) * 4;
        *(float4*)&ksb[r * LDK + c4] = cvt4(*(const float4*)&kg[(size_t)r * DH + c4]);
        *(float4*)&vsb[r * LDV + c4] = cvt4(*(const float4*)&vg[(size_t)r * DH + c4]);
    }
    __syncthreads();

    const int wrow = qt * QROWS2 + wid * 16;   // warp's first global q row
    float mrow0 = -INFINITY, mrow1 = -INFINITY;
    float lrow0 = 0.f, lrow1 = 0.f;
    float o[8][4];
#pragma unroll
    for (int nc = 0; nc < 8; nc++)
#pragma unroll
        for (int v = 0; v < 4; v++) o[nc][v] = 0.f;

    const int ktmax = 4 * qt + 3;
    for (int kt = 0; kt <= ktmax; kt++) {
        const int buf = kt & 1;
        const bool more = (kt < ktmax);
        float* kcur = ksb + buf * 64 * LDK;
        float* vcur = vsb + buf * 64 * LDV;

        // prefetch next tile into registers (latency overlaps compute)
        float4 pk[2], pv[2];
        if (more) {
#pragma unroll
            for (int l = 0; l < 2; l++) {
                int idx = tid + l * 512;
                int r   = idx >> 4;
                int c4  = (idx & 15) * 4;
                pk[l] = *(const float4*)&kg[(size_t)((kt + 1) * 64 + r) * DH + c4];
                pv[l] = *(const float4*)&vg[(size_t)((kt + 1) * 64 + r) * DH + c4];
            }
        }

        if (kt * 64 <= wrow + 15) {   // warp has unmasked work in this tile
            // ---- S = Q K^T ----
            float s[8][4];
#pragma unroll
            for (int nc = 0; nc < 8; nc++)
#pragma unroll
                for (int v = 0; v < 4; v++) s[nc][v] = 0.f;
#pragma unroll
            for (int kk8 = 0; kk8 < 8; kk8++) {
                const int kk = kk8 * 8;
                uint32_t a[4];
                a[0] = __float_as_uint(qs[(wid * 16 + g    ) * LDQ + kk + tig]);
                a[1] = __float_as_uint(qs[(wid * 16 + g + 8) * LDQ + kk + tig]);
                a[2] = __float_as_uint(qs[(wid * 16 + g    ) * LDQ + kk + tig + 4]);
                a[3] = __float_as_uint(qs[(wid * 16 + g + 8) * LDQ + kk + tig + 4]);
#pragma unroll
                for (int nc = 0; nc < 8; nc++) {
                    uint32_t b[2];
                    b[0] = __float_as_uint(kcur[(nc * 8 + g) * LDK + kk + tig]);
                    b[1] = __float_as_uint(kcur[(nc * 8 + g) * LDK + kk + tig + 4]);
                    mma_tf32(s[nc], a, b);
                }
            }

            // ---- causal mask (boundary tiles) ----
            if (kt * 64 + 63 > wrow) {
#pragma unroll
                for (int nc = 0; nc < 8; nc++) {
                    int col = kt * 64 + nc * 8 + 2 * tig;
                    if (col     > wrow + g)     s[nc][0] = -INFINITY;
                    if (col + 1 > wrow + g)     s[nc][1] = -INFINITY;
                    if (col     > wrow + g + 8) s[nc][2] = -INFINITY;
                    if (col + 1 > wrow + g + 8) s[nc][3] = -INFINITY;
                }
            }

            // ---- warp-local online softmax ----
            float t0 = -INFINITY, t1 = -INFINITY;
#pragma unroll
            for (int nc = 0; nc < 8; nc++) {
                t0 = fmaxf(t0, fmaxf(s[nc][0], s[nc][1]));
                t1 = fmaxf(t1, fmaxf(s[nc][2], s[nc][3]));
            }
            t0 = fmaxf(t0, __shfl_xor_sync(0xffffffffu, t0, 1));
            t0 = fmaxf(t0, __shfl_xor_sync(0xffffffffu, t0, 2));
            t1 = fmaxf(t1, __shfl_xor_sync(0xffffffffu, t1, 1));
            t1 = fmaxf(t1, __shfl_xor_sync(0xffffffffu, t1, 2));
            float mn0 = fmaxf(mrow0, t0);
            float mn1 = fmaxf(mrow1, t1);
            float sc0 = __expf(mrow0 - mn0);
            float sc1 = __expf(mrow1 - mn1);
            mrow0 = mn0; mrow1 = mn1;

            float rs0 = 0.f, rs1 = 0.f;
#pragma unroll
            for (int nc = 0; nc < 8; nc++) {
                float p0 = f2tf32f(__expf(s[nc][0] - mn0));
                float p1 = f2tf32f(__expf(s[nc][1] - mn0));
                float p2 = f2tf32f(__expf(s[nc][2] - mn1));
                float p3 = f2tf32f(__expf(s[nc][3] - mn1));
                rs0 += p0 + p1;
                rs1 += p2 + p3;
                *(float2*)&ps[(g    ) * LDP + nc * 8 + 2 * tig] = make_float2(p0, p1);
                *(float2*)&ps[(g + 8) * LDP + nc * 8 + 2 * tig] = make_float2(p2, p3);
            }
            rs0 += __shfl_xor_sync(0xffffffffu, rs0, 1);
            rs0 += __shfl_xor_sync(0xffffffffu, rs0, 2);
            rs1 += __shfl_xor_sync(0xffffffffu, rs1, 1);
            rs1 += __shfl_xor_sync(0xffffffffu, rs1, 2);
            lrow0 = lrow0 * sc0 + rs0;
            lrow1 = lrow1 * sc1 + rs1;
#pragma unroll
            for (int nc = 0; nc < 8; nc++) {
                o[nc][0] *= sc0; o[nc][1] *= sc0;
                o[nc][2] *= sc1; o[nc][3] *= sc1;
            }
            __syncwarp();

            // ---- O += P V ----
#pragma unroll
            for (int kk8 = 0; kk8 < 8; kk8++) {
                const int kk = kk8 * 8;
                uint32_t a[4];
                a[0] = __float_as_uint(ps[(g    ) * LDP + kk + tig]);
                a[1] = __float_as_uint(ps[(g + 8) * LDP + kk + tig]);
                a[2] = __float_as_uint(ps[(g    ) * LDP + kk + tig + 4]);
                a[3] = __float_as_uint(ps[(g + 8) * LDP + kk + tig + 4]);
#pragma unroll
                for (int nc = 0; nc < 8; nc++) {
                    uint32_t b[2];
                    b[0] = __float_as_uint(vcur[(kk + tig    ) * LDV + nc * 8 + g]);
                    b[1] = __float_as_uint(vcur[(kk + tig + 4) * LDV + nc * 8 + g]);
                    mma_tf32(o[nc], a, b);
                }
            }
        }

        if (more) {
            float* knxt = ksb + (buf ^ 1) * 64 * LDK;
            float* vnxt = vsb + (buf ^ 1) * 64 * LDV;
#pragma unroll
            for (int l = 0; l < 2; l++) {
                int idx = tid + l * 512;
                int r   = idx >> 4;
                int c4  = (idx & 15) * 4;
                *(float4*)&knxt[r * LDK + c4] = cvt4(pk[l]);
                *(float4*)&vnxt[r * LDV + c4] = cvt4(pv[l]);
            }
            __syncthreads();
        }
    }

    // ---- normalize & write to g_att [B,T,C] ----
    const int b = bh >> 4;
    const int h = bh & 15;
    const float inv0 = 1.f / lrow0;
    const float inv1 = 1.f / lrow1;
    const int t0r = wrow + g;
    const int t1r = wrow + g + 8;
#pragma unroll
    for (int nc = 0; nc < 8; nc++) {
        int d = h * DH + nc * 8 + 2 * tig;
        *(float2*)&g_att[((size_t)b * TLEN + t0r) * CDIM + d] =
            make_float2(o[nc][0] * inv0, o[nc][1] * inv0);
        *(float2*)&g_att[((size_t)b * TLEN + t1r) * CDIM + d] =
            make_float2(o[nc][2] * inv1, o[nc][3] * inv1);
    }
}

// ----------------------------------------------------------------------------
extern "C" void kernel_launch(void* const* d_in, const int* in_sizes, int n_in,
                              void* d_out, int out_size)
{
    const float* x  = (const float*)d_in[0];
    const float* Wq = (const float*)d_in[1];
    const float* Wk = (const float*)d_in[2];
    const float* Wv = (const float*)d_in[3];
    const float* Wo = (const float*)d_in[4];
    float* out = (float*)d_out;

    gemm_mma_kernel<1><<<dim3(CDIM / 128, MROWS / 128, 3), 256>>>(
        x, Wq, Wk, Wv, nullptr);

    cudaFuncSetAttribute(attn_mma2_kernel,
                         cudaFuncAttributeMaxDynamicSharedMemorySize, ATT2_SMEM);
    attn_mma2_kernel<<<dim3(TLEN / QROWS2, BDIM * NH), 512, ATT2_SMEM>>>();

    gemm_mma_kernel<0><<<dim3(CDIM / 128, MROWS / 128, 1), 256>>>(
        nullptr, Wo, nullptr, nullptr, out);
}

// round 8
// speedup vs baseline: 1.0867x; 1.0867x over previous
#include <cuda_runtime.h>
#include <cstdint>
#include <math.h>

#define BDIM 2
#define TLEN 2048
#define CDIM 1024
#define NH   16
#define DH   64
#define MROWS (BDIM * TLEN)   // 4096

// Scratch (allocation-free rule: __device__ globals)
__device__ float g_q[(size_t)BDIM * NH * TLEN * DH];
__device__ float g_k[(size_t)BDIM * NH * TLEN * DH];
__device__ float g_v[(size_t)BDIM * NH * TLEN * DH];
__device__ float g_att[(size_t)MROWS * CDIM];       // [B,T,C], tf32-rounded
__device__ float g_xr[(size_t)MROWS * CDIM];        // tf32-rounded x
__device__ float g_wr[4][(size_t)CDIM * CDIM];      // tf32-rounded Wq,Wk,Wv,Wo

// ============================================================================
// helpers
// ============================================================================
__device__ __forceinline__ float f2tf32f(float f) {
    uint32_t r;
    asm("cvt.rna.tf32.f32 %0, %1;" : "=r"(r) : "f"(f));
    return __uint_as_float(r);
}
__device__ __forceinline__ float4 cvt4(float4 v) {
    return make_float4(f2tf32f(v.x), f2tf32f(v.y), f2tf32f(v.z), f2tf32f(v.w));
}
__device__ __forceinline__ void mma_tf32(float* d, const uint32_t* a,
                                         const uint32_t* b) {
    asm volatile(
        "mma.sync.aligned.m16n8k8.row.col.f32.tf32.tf32.f32 "
        "{%0,%1,%2,%3}, {%4,%5,%6,%7}, {%8,%9}, {%0,%1,%2,%3};"
        : "+f"(d[0]), "+f"(d[1]), "+f"(d[2]), "+f"(d[3])
        : "r"(a[0]), "r"(a[1]), "r"(a[2]), "r"(a[3]), "r"(b[0]), "r"(b[1]));
}
__device__ __forceinline__ uint32_t smem_u32(const void* p) {
    uint32_t a;
    asm("{ .reg .u64 t; cvta.to.shared.u64 t, %1; cvt.u32.u64 %0, t; }"
        : "=r"(a) : "l"(p));
    return a;
}
__device__ __forceinline__ void cp_async16(uint32_t saddr, const void* gptr) {
    asm volatile("cp.async.ca.shared.global [%0], [%1], 16;"
                 :: "r"(saddr), "l"(gptr) : "memory");
}
__device__ __forceinline__ void cp_commit() {
    asm volatile("cp.async.commit_group;" ::: "memory");
}

// ============================================================================
// preround: tf32-round x and the 4 weight matrices into scratch
// ============================================================================
__global__ void __launch_bounds__(256) preround_kernel(
    const float* __restrict__ x,  const float* __restrict__ Wq,
    const float* __restrict__ Wk, const float* __restrict__ Wv,
    const float* __restrict__ Wo)
{
    const int t = blockIdx.y;
    const float* src;
    float* dst;
    int n;
    if (t == 0) { src = x; dst = g_xr; n = MROWS * CDIM / 4; }
    else {
        src = (t == 1) ? Wq : (t == 2) ? Wk : (t == 3) ? Wv : Wo;
        dst = g_wr[t - 1];
        n = CDIM * CDIM / 4;
    }
    int idx = blockIdx.x * 256 + threadIdx.x;
    if (idx < n) ((float4*)dst)[idx] = cvt4(((const float4*)src)[idx]);
}

// ============================================================================
// cp.async 3-stage tf32 mma.sync GEMM: C[m,n] = sum_k A[m,k] * W[n,k]
// CTA 128x128, BK=32, 8 warps (4x2), warp tile 32x64. Inputs pre-rounded.
// ============================================================================
#define BK2 32
#define LDT2 36
#define STAGES 3
#define NSTEP2 (CDIM / BK2)     // 32
#define GSMEM2 (STAGES * 128 * LDT2 * 2 * 4)   // 110592 B

template <int SCATTER>
__global__ void __launch_bounds__(256, 2) gemm_cp_kernel(float* __restrict__ Cout)
{
    extern __shared__ float smf[];
    const int K = CDIM;
    float* As = smf;                           // [STAGES][128][LDT2]
    float* Ws = smf + STAGES * 128 * LDT2;

    const float* Ap = SCATTER ? g_xr : g_att;
    const float* W  = g_wr[SCATTER ? blockIdx.z : 3];
    float* dst;
    if (SCATTER) {
        int z = blockIdx.z;
        dst = (z == 0) ? g_q : (z == 1) ? g_k : g_v;
    } else {
        dst = Cout;
    }

    const int bm0  = blockIdx.y * 128;
    const int bn0  = blockIdx.x * 128;
    const int tid  = threadIdx.x;
    const int lane = tid & 31;
    const int wid  = tid >> 5;
    const int g    = lane >> 2;
    const int tig  = lane & 3;
    const int wm   = (wid & 3) * 32;
    const int wn   = (wid >> 2) * 64;

    const uint32_t sbA = smem_u32(As);
    const uint32_t sbW = smem_u32(Ws);

    // cp.async coords: per matrix per tile 1024 float4 chunks, 4 per thread
    const int crow = tid >> 3;            // 0..31 base row block? no: idx>>3
    (void)crow;

    float d[2][8][4];
#pragma unroll
    for (int mc = 0; mc < 2; mc++)
#pragma unroll
        for (int nc = 0; nc < 8; nc++)
#pragma unroll
            for (int v = 0; v < 4; v++) d[mc][nc][v] = 0.f;

    // issue tile t into slot
    auto issue = [&](int t, int slot) {
        const int k0 = t * BK2;
        const uint32_t ab = sbA + slot * 128 * LDT2 * 4;
        const uint32_t wb = sbW + slot * 128 * LDT2 * 4;
#pragma unroll
        for (int l = 0; l < 4; l++) {
            int idx = tid + l * 256;      // 0..1023
            int r   = idx >> 3;           // 0..127
            int c   = idx & 7;            // float4 within row
            uint32_t so = (uint32_t)(r * LDT2 + c * 4) * 4;
            cp_async16(ab + so, &Ap[(size_t)(bm0 + r) * K + k0 + c * 4]);
            cp_async16(wb + so, &W [(size_t)(bn0 + r) * K + k0 + c * 4]);
        }
        cp_commit();
    };

    issue(0, 0);
    issue(1, 1);

    for (int s = 0; s < NSTEP2; s++) {
        if (s + 1 < NSTEP2) asm volatile("cp.async.wait_group 1;" ::: "memory");
        else                asm volatile("cp.async.wait_group 0;" ::: "memory");
        __syncthreads();
        if (s + 2 < NSTEP2) issue(s + 2, (s + 2) % STAGES);

        const float* Ab = As + (s % STAGES) * 128 * LDT2;
        const float* Wb = Ws + (s % STAGES) * 128 * LDT2;
#pragma unroll
        for (int kk8 = 0; kk8 < 4; kk8++) {
            const int kk = kk8 * 8;
            uint32_t a[2][4];
#pragma unroll
            for (int mc = 0; mc < 2; mc++) {
                int row = wm + mc * 16 + g;
                a[mc][0] = __float_as_uint(Ab[(row    ) * LDT2 + kk + tig]);
                a[mc][1] = __float_as_uint(Ab[(row + 8) * LDT2 + kk + tig]);
                a[mc][2] = __float_as_uint(Ab[(row    ) * LDT2 + kk + tig + 4]);
                a[mc][3] = __float_as_uint(Ab[(row + 8) * LDT2 + kk + tig + 4]);
            }
#pragma unroll
            for (int nc = 0; nc < 8; nc++) {
                uint32_t b[2];
                int row = wn + nc * 8 + g;
                b[0] = __float_as_uint(Wb[row * LDT2 + kk + tig]);
                b[1] = __float_as_uint(Wb[row * LDT2 + kk + tig + 4]);
                mma_tf32(d[0][nc], a[0], b);
                mma_tf32(d[1][nc], a[1], b);
            }
        }
    }

    // Epilogue: fragment rows {g, g+8}, cols {2*tig, 2*tig+1}
#pragma unroll
    for (int mc = 0; mc < 2; mc++) {
#pragma unroll
        for (int nc = 0; nc < 8; nc++) {
            int n = bn0 + wn + nc * 8 + tig * 2;
#pragma unroll
            for (int rr = 0; rr < 2; rr++) {
                int m = bm0 + wm + mc * 16 + g + rr * 8;
                float2 val = make_float2(d[mc][nc][rr * 2 + 0], d[mc][nc][rr * 2 + 1]);
                if (SCATTER) {
                    int bb = m >> 11;
                    int tt = m & 2047;
                    int hh = n >> 6;
                    int dd = n & 63;
                    *(float2*)&dst[(((size_t)bb * NH + hh) * TLEN + tt) * DH + dd] = val;
                } else {
                    *(float2*)&dst[(size_t)m * CDIM + n] = val;
                }
            }
        }
    }
}

// ============================================================================
// tf32 mma.sync causal flash attention (round-6 proven version).
// CTA = 128 q rows, 8 warps x 16 rows, warp-local softmax, 2 CTAs/SM.
// Epilogue writes tf32-rounded g_att (feeds cp.async gemm<0>).
// ============================================================================
#define LDQ 68
#define LDK 68
#define LDV 72
#define LDP 68
#define QROWS 128
#define ATT_SMEM (26368 * 4)

__global__ void __launch_bounds__(256, 2) attn_mma_kernel()
{
    extern __shared__ float sm[];
    float* qs = sm;                         // [128][LDQ]
    float* ks = qs + QROWS * LDQ;           // [64][LDK]
    float* vs = ks + 64 * LDK;              // [64][LDV]
    float* psa = vs + 64 * LDV;             // [8][16][LDP]

    const int qt = (gridDim.x - 1) - blockIdx.x;   // big tiles first
    const int bh = blockIdx.y;
    const float* qg = g_q + (size_t)bh * TLEN * DH;
    const float* kg = g_k + (size_t)bh * TLEN * DH;
    const float* vg = g_v + (size_t)bh * TLEN * DH;

    const int tid  = threadIdx.x;
    const int lane = tid & 31;
    const int wid  = tid >> 5;
    const int g    = lane >> 2;
    const int tig  = lane & 3;
    float* ps = psa + wid * 16 * LDP;

#pragma unroll
    for (int l = 0; l < 8; l++) {
        int idx = tid + l * 256;
        int r   = idx >> 4;
        int c4  = (idx & 15) * 4;
        float4 v = *(const float4*)&qg[(size_t)(qt * QROWS + r) * DH + c4];
        float4 t = make_float4(f2tf32f(v.x * 0.125f), f2tf32f(v.y * 0.125f),
                               f2tf32f(v.z * 0.125f), f2tf32f(v.w * 0.125f));
        *(float4*)&qs[r * LDQ + c4] = t;
    }

    const int wrow = qt * QROWS + wid * 16;
    float mrow0 = -INFINITY, mrow1 = -INFINITY;
    float lrow0 = 0.f, lrow1 = 0.f;
    float o[8][4];
#pragma unroll
    for (int nc = 0; nc < 8; nc++)
#pragma unroll
        for (int v = 0; v < 4; v++) o[nc][v] = 0.f;

    __syncthreads();

    const int ktmax = 2 * qt + 1;
    for (int kt = 0; kt <= ktmax; kt++) {
#pragma unroll
        for (int l = 0; l < 4; l++) {
            int idx = tid + l * 256;
            int r   = idx >> 4;
            int c4  = (idx & 15) * 4;
            *(float4*)&ks[r * LDK + c4] =
                cvt4(*(const float4*)&kg[(size_t)(kt * 64 + r) * DH + c4]);
            *(float4*)&vs[r * LDV + c4] =
                cvt4(*(const float4*)&vg[(size_t)(kt * 64 + r) * DH + c4]);
        }
        __syncthreads();

        if (kt * 64 <= wrow + 15) {
            float s[8][4];
#pragma unroll
            for (int nc = 0; nc < 8; nc++)
#pragma unroll
                for (int v = 0; v < 4; v++) s[nc][v] = 0.f;
#pragma unroll
            for (int kk8 = 0; kk8 < 8; kk8++) {
                const int kk = kk8 * 8;
                uint32_t a[4];
                a[0] = __float_as_uint(qs[(wid * 16 + g    ) * LDQ + kk + tig]);
                a[1] = __float_as_uint(qs[(wid * 16 + g + 8) * LDQ + kk + tig]);
                a[2] = __float_as_uint(qs[(wid * 16 + g    ) * LDQ + kk + tig + 4]);
                a[3] = __float_as_uint(qs[(wid * 16 + g + 8) * LDQ + kk + tig + 4]);
#pragma unroll
                for (int nc = 0; nc < 8; nc++) {
                    uint32_t b[2];
                    b[0] = __float_as_uint(ks[(nc * 8 + g) * LDK + kk + tig]);
                    b[1] = __float_as_uint(ks[(nc * 8 + g) * LDK + kk + tig + 4]);
                    mma_tf32(s[nc], a, b);
                }
            }

            if (kt * 64 + 63 > wrow) {
#pragma unroll
                for (int nc = 0; nc < 8; nc++) {
                    int col = kt * 64 + nc * 8 + 2 * tig;
                    if (col     > wrow + g)     s[nc][0] = -INFINITY;
                    if (col + 1 > wrow + g)     s[nc][1] = -INFINITY;
                    if (col     > wrow + g + 8) s[nc][2] = -INFINITY;
                    if (col + 1 > wrow + g + 8) s[nc][3] = -INFINITY;
                }
            }

            float t0 = -INFINITY, t1 = -INFINITY;
#pragma unroll
            for (int nc = 0; nc < 8; nc++) {
                t0 = fmaxf(t0, fmaxf(s[nc][0], s[nc][1]));
                t1 = fmaxf(t1, fmaxf(s[nc][2], s[nc][3]));
            }
            t0 = fmaxf(t0, __shfl_xor_sync(0xffffffffu, t0, 1));
            t0 = fmaxf(t0, __shfl_xor_sync(0xffffffffu, t0, 2));
            t1 = fmaxf(t1, __shfl_xor_sync(0xffffffffu, t1, 1));
            t1 = fmaxf(t1, __shfl_xor_sync(0xffffffffu, t1, 2));
            float mn0 = fmaxf(mrow0, t0);
            float mn1 = fmaxf(mrow1, t1);
            float sc0 = __expf(mrow0 - mn0);
            float sc1 = __expf(mrow1 - mn1);
            mrow0 = mn0; mrow1 = mn1;

            float rs0 = 0.f, rs1 = 0.f;
#pragma unroll
            for (int nc = 0; nc < 8; nc++) {
                float p0 = f2tf32f(__expf(s[nc][0] - mn0));
                float p1 = f2tf32f(__expf(s[nc][1] - mn0));
                float p2 = f2tf32f(__expf(s[nc][2] - mn1));
                float p3 = f2tf32f(__expf(s[nc][3] - mn1));
                rs0 += p0 + p1;
                rs1 += p2 + p3;
                *(float2*)&ps[(g    ) * LDP + nc * 8 + 2 * tig] = make_float2(p0, p1);
                *(float2*)&ps[(g + 8) * LDP + nc * 8 + 2 * tig] = make_float2(p2, p3);
            }
            rs0 += __shfl_xor_sync(0xffffffffu, rs0, 1);
            rs0 += __shfl_xor_sync(0xffffffffu, rs0, 2);
            rs1 += __shfl_xor_sync(0xffffffffu, rs1, 1);
            rs1 += __shfl_xor_sync(0xffffffffu, rs1, 2);
            lrow0 = lrow0 * sc0 + rs0;
            lrow1 = lrow1 * sc1 + rs1;
#pragma unroll
            for (int nc = 0; nc < 8; nc++) {
                o[nc][0] *= sc0; o[nc][1] *= sc0;
                o[nc][2] *= sc1; o[nc][3] *= sc1;
            }
            __syncwarp();

#pragma unroll
            for (int kk8 = 0; kk8 < 8; kk8++) {
                const int kk = kk8 * 8;
                uint32_t a[4];
                a[0] = __float_as_uint(ps[(g    ) * LDP + kk + tig]);
                a[1] = __float_as_uint(ps[(g + 8) * LDP + kk + tig]);
                a[2] = __float_as_uint(ps[(g    ) * LDP + kk + tig + 4]);
                a[3] = __float_as_uint(ps[(g + 8) * LDP + kk + tig + 4]);
#pragma unroll
                for (int nc = 0; nc < 8; nc++) {
                    uint32_t b[2];
                    b[0] = __float_as_uint(vs[(kk + tig    ) * LDV + nc * 8 + g]);
                    b[1] = __float_as_uint(vs[(kk + tig + 4) * LDV + nc * 8 + g]);
                    mma_tf32(o[nc], a, b);
                }
            }
        }
        __syncthreads();
    }

    // normalize, tf32-round, write g_att [B,T,C]
    const int b = bh >> 4;
    const int h = bh & 15;
    const float inv0 = 1.f / lrow0;
    const float inv1 = 1.f / lrow1;
    const int t0r = wrow + g;
    const int t1r = wrow + g + 8;
#pragma unroll
    for (int nc = 0; nc < 8; nc++) {
        int d = h * DH + nc * 8 + 2 * tig;
        *(float2*)&g_att[((size_t)b * TLEN + t0r) * CDIM + d] =
            make_float2(f2tf32f(o[nc][0] * inv0), f2tf32f(o[nc][1] * inv0));
        *(float2*)&g_att[((size_t)b * TLEN + t1r) * CDIM + d] =
            make_float2(f2tf32f(o[nc][2] * inv1), f2tf32f(o[nc][3] * inv1));
    }
}

// ----------------------------------------------------------------------------
extern "C" void kernel_launch(void* const* d_in, const int* in_sizes, int n_in,
                              void* d_out, int out_size)
{
    const float* x  = (const float*)d_in[0];
    const float* Wq = (const float*)d_in[1];
    const float* Wk = (const float*)d_in[2];
    const float* Wv = (const float*)d_in[3];
    const float* Wo = (const float*)d_in[4];
    float* out = (float*)d_out;

    preround_kernel<<<dim3(4096, 5), 256>>>(x, Wq, Wk, Wv, Wo);

    cudaFuncSetAttribute(gemm_cp_kernel<1>,
                         cudaFuncAttributeMaxDynamicSharedMemorySize, GSMEM2);
    cudaFuncSetAttribute(gemm_cp_kernel<0>,
                         cudaFuncAttributeMaxDynamicSharedMemorySize, GSMEM2);

    gemm_cp_kernel<1><<<dim3(CDIM / 128, MROWS / 128, 3), 256, GSMEM2>>>(nullptr);

    cudaFuncSetAttribute(attn_mma_kernel,
                         cudaFuncAttributeMaxDynamicSharedMemorySize, ATT_SMEM);
    attn_mma_kernel<<<dim3(TLEN / QROWS, BDIM * NH), 256, ATT_SMEM>>>();

    gemm_cp_kernel<0><<<dim3(CDIM / 128, MROWS / 128, 1), 256, GSMEM2>>>(out);
}

// round 9
// speedup vs baseline: 1.1486x; 1.0570x over previous
#include <cuda_runtime.h>
#include <cstdint>
#include <math.h>

#define BDIM 2
#define TLEN 2048
#define CDIM 1024
#define NH   16
#define DH   64
#define MROWS (BDIM * TLEN)   // 4096

// Scratch (allocation-free rule: __device__ globals)
__device__ float g_q[(size_t)BDIM * NH * TLEN * DH];
__device__ float g_k[(size_t)BDIM * NH * TLEN * DH];
__device__ float g_v[(size_t)BDIM * NH * TLEN * DH];
__device__ float g_att[(size_t)MROWS * CDIM];       // [B,T,C], tf32-rounded
__device__ float g_xr[(size_t)MROWS * CDIM];        // tf32-rounded x
__device__ float g_wr[4][(size_t)CDIM * CDIM];      // tf32-rounded Wq,Wk,Wv,Wo

// ============================================================================
// helpers
// ============================================================================
__device__ __forceinline__ float f2tf32f(float f) {
    uint32_t r;
    asm("cvt.rna.tf32.f32 %0, %1;" : "=r"(r) : "f"(f));
    return __uint_as_float(r);
}
__device__ __forceinline__ float4 cvt4(float4 v) {
    return make_float4(f2tf32f(v.x), f2tf32f(v.y), f2tf32f(v.z), f2tf32f(v.w));
}
__device__ __forceinline__ void mma_tf32(float* d, const uint32_t* a,
                                         const uint32_t* b) {
    asm volatile(
        "mma.sync.aligned.m16n8k8.row.col.f32.tf32.tf32.f32 "
        "{%0,%1,%2,%3}, {%4,%5,%6,%7}, {%8,%9}, {%0,%1,%2,%3};"
        : "+f"(d[0]), "+f"(d[1]), "+f"(d[2]), "+f"(d[3])
        : "r"(a[0]), "r"(a[1]), "r"(a[2]), "r"(a[3]), "r"(b[0]), "r"(b[1]));
}
__device__ __forceinline__ uint32_t smem_u32(const void* p) {
    uint32_t a;
    asm("{ .reg .u64 t; cvta.to.shared.u64 t, %1; cvt.u32.u64 %0, t; }"
        : "=r"(a) : "l"(p));
    return a;
}
__device__ __forceinline__ void cp_async16(uint32_t saddr, const void* gptr) {
    asm volatile("cp.async.ca.shared.global [%0], [%1], 16;"
                 :: "r"(saddr), "l"(gptr) : "memory");
}
__device__ __forceinline__ void cp_commit() {
    asm volatile("cp.async.commit_group;" ::: "memory");
}

// ============================================================================
// preround: tf32-round x and the 4 weight matrices into scratch
// ============================================================================
__global__ void __launch_bounds__(256) preround_kernel(
    const float* __restrict__ x,  const float* __restrict__ Wq,
    const float* __restrict__ Wk, const float* __restrict__ Wv,
    const float* __restrict__ Wo)
{
    const int t = blockIdx.y;
    const float* src;
    float* dst;
    int n;
    if (t == 0) { src = x; dst = g_xr; n = MROWS * CDIM / 4; }
    else {
        src = (t == 1) ? Wq : (t == 2) ? Wk : (t == 3) ? Wv : Wo;
        dst = g_wr[t - 1];
        n = CDIM * CDIM / 4;
    }
    int idx = blockIdx.x * 256 + threadIdx.x;
    if (idx < n) ((float4*)dst)[idx] = cvt4(((const float4*)src)[idx]);
}

// ============================================================================
// cp.async 3-stage tf32 mma.sync GEMM (unchanged from round 8)
// ============================================================================
#define BK2 32
#define LDT2 36
#define STAGES 3
#define NSTEP2 (CDIM / BK2)     // 32
#define GSMEM2 (STAGES * 128 * LDT2 * 2 * 4)   // 110592 B

template <int SCATTER>
__global__ void __launch_bounds__(256, 2) gemm_cp_kernel(float* __restrict__ Cout)
{
    extern __shared__ float smf[];
    const int K = CDIM;
    float* As = smf;                           // [STAGES][128][LDT2]
    float* Ws = smf + STAGES * 128 * LDT2;

    const float* Ap = SCATTER ? g_xr : g_att;
    const float* W  = g_wr[SCATTER ? blockIdx.z : 3];
    float* dst;
    if (SCATTER) {
        int z = blockIdx.z;
        dst = (z == 0) ? g_q : (z == 1) ? g_k : g_v;
    } else {
        dst = Cout;
    }

    const int bm0  = blockIdx.y * 128;
    const int bn0  = blockIdx.x * 128;
    const int tid  = threadIdx.x;
    const int lane = tid & 31;
    const int wid  = tid >> 5;
    const int g    = lane >> 2;
    const int tig  = lane & 3;
    const int wm   = (wid & 3) * 32;
    const int wn   = (wid >> 2) * 64;

    const uint32_t sbA = smem_u32(As);
    const uint32_t sbW = smem_u32(Ws);

    float d[2][8][4];
#pragma unroll
    for (int mc = 0; mc < 2; mc++)
#pragma unroll
        for (int nc = 0; nc < 8; nc++)
#pragma unroll
            for (int v = 0; v < 4; v++) d[mc][nc][v] = 0.f;

    auto issue = [&](int t, int slot) {
        const int k0 = t * BK2;
        const uint32_t ab = sbA + slot * 128 * LDT2 * 4;
        const uint32_t wb = sbW + slot * 128 * LDT2 * 4;
#pragma unroll
        for (int l = 0; l < 4; l++) {
            int idx = tid + l * 256;      // 0..1023
            int r   = idx >> 3;           // 0..127
            int c   = idx & 7;
            uint32_t so = (uint32_t)(r * LDT2 + c * 4) * 4;
            cp_async16(ab + so, &Ap[(size_t)(bm0 + r) * K + k0 + c * 4]);
            cp_async16(wb + so, &W [(size_t)(bn0 + r) * K + k0 + c * 4]);
        }
        cp_commit();
    };

    issue(0, 0);
    issue(1, 1);

    for (int s = 0; s < NSTEP2; s++) {
        if (s + 1 < NSTEP2) asm volatile("cp.async.wait_group 1;" ::: "memory");
        else                asm volatile("cp.async.wait_group 0;" ::: "memory");
        __syncthreads();
        if (s + 2 < NSTEP2) issue(s + 2, (s + 2) % STAGES);

        const float* Ab = As + (s % STAGES) * 128 * LDT2;
        const float* Wb = Ws + (s % STAGES) * 128 * LDT2;
#pragma unroll
        for (int kk8 = 0; kk8 < 4; kk8++) {
            const int kk = kk8 * 8;
            uint32_t a[2][4];
#pragma unroll
            for (int mc = 0; mc < 2; mc++) {
                int row = wm + mc * 16 + g;
                a[mc][0] = __float_as_uint(Ab[(row    ) * LDT2 + kk + tig]);
                a[mc][1] = __float_as_uint(Ab[(row + 8) * LDT2 + kk + tig]);
                a[mc][2] = __float_as_uint(Ab[(row    ) * LDT2 + kk + tig + 4]);
                a[mc][3] = __float_as_uint(Ab[(row + 8) * LDT2 + kk + tig + 4]);
            }
#pragma unroll
            for (int nc = 0; nc < 8; nc++) {
                uint32_t b[2];
                int row = wn + nc * 8 + g;
                b[0] = __float_as_uint(Wb[row * LDT2 + kk + tig]);
                b[1] = __float_as_uint(Wb[row * LDT2 + kk + tig + 4]);
                mma_tf32(d[0][nc], a[0], b);
                mma_tf32(d[1][nc], a[1], b);
            }
        }
    }

#pragma unroll
    for (int mc = 0; mc < 2; mc++) {
#pragma unroll
        for (int nc = 0; nc < 8; nc++) {
            int n = bn0 + wn + nc * 8 + tig * 2;
#pragma unroll
            for (int rr = 0; rr < 2; rr++) {
                int m = bm0 + wm + mc * 16 + g + rr * 8;
                float2 val = make_float2(d[mc][nc][rr * 2 + 0], d[mc][nc][rr * 2 + 1]);
                if (SCATTER) {
                    int bb = m >> 11;
                    int tt = m & 2047;
                    int hh = n >> 6;
                    int dd = n & 63;
                    *(float2*)&dst[(((size_t)bb * NH + hh) * TLEN + tt) * DH + dd] = val;
                } else {
                    *(float2*)&dst[(size_t)m * CDIM + n] = val;
                }
            }
        }
    }
}

// ============================================================================
// tf32 mma.sync causal flash attention v3 — register-resident P.
// k-permutation sigma(8j+t) = 8j+2t (t<4) / 8j+2(t-4)+1 (t>=4) makes the PV
// A-fragment equal the softmax registers: a = {s[j][0], s[j][2], s[j][1],
// s[j][3]}; V B-fragment reads rows 8j+2*tig(+1), conflict-free at LDV=68.
// No P smem, no syncwarp. smem 70KB -> 3 CTAs/SM.
// ============================================================================
#define LDQ 68
#define LDK 68
#define LDV 68
#define QROWS 128
// floats: qs 128*68 + ks 64*68 + vs 64*68 = 8704 + 4352 + 4352 = 17408
#define ATT_SMEM (17408 * 4)    // 69632 B

__global__ void __launch_bounds__(256, 3) attn_mma_kernel()
{
    extern __shared__ float sm[];
    float* qs = sm;                         // [128][LDQ]
    float* ks = qs + QROWS * LDQ;           // [64][LDK]
    float* vs = ks + 64 * LDK;              // [64][LDV]

    const int qt = (gridDim.x - 1) - blockIdx.x;   // big tiles first
    const int bh = blockIdx.y;
    const float* qg = g_q + (size_t)bh * TLEN * DH;
    const float* kg = g_k + (size_t)bh * TLEN * DH;
    const float* vg = g_v + (size_t)bh * TLEN * DH;

    const int tid  = threadIdx.x;
    const int lane = tid & 31;
    const int wid  = tid >> 5;
    const int g    = lane >> 2;
    const int tig  = lane & 3;

#pragma unroll
    for (int l = 0; l < 8; l++) {
        int idx = tid + l * 256;
        int r   = idx >> 4;
        int c4  = (idx & 15) * 4;
        float4 v = *(const float4*)&qg[(size_t)(qt * QROWS + r) * DH + c4];
        float4 t = make_float4(f2tf32f(v.x * 0.125f), f2tf32f(v.y * 0.125f),
                               f2tf32f(v.z * 0.125f), f2tf32f(v.w * 0.125f));
        *(float4*)&qs[r * LDQ + c4] = t;
    }

    const int wrow = qt * QROWS + wid * 16;
    float mrow0 = -INFINITY, mrow1 = -INFINITY;
    float lrow0 = 0.f, lrow1 = 0.f;
    float o[8][4];
#pragma unroll
    for (int nc = 0; nc < 8; nc++)
#pragma unroll
        for (int v = 0; v < 4; v++) o[nc][v] = 0.f;

    __syncthreads();

    const int ktmax = 2 * qt + 1;
    for (int kt = 0; kt <= ktmax; kt++) {
#pragma unroll
        for (int l = 0; l < 4; l++) {
            int idx = tid + l * 256;
            int r   = idx >> 4;
            int c4  = (idx & 15) * 4;
            *(float4*)&ks[r * LDK + c4] =
                cvt4(*(const float4*)&kg[(size_t)(kt * 64 + r) * DH + c4]);
            *(float4*)&vs[r * LDV + c4] =
                cvt4(*(const float4*)&vg[(size_t)(kt * 64 + r) * DH + c4]);
        }
        __syncthreads();

        if (kt * 64 <= wrow + 15) {
            // ---- S = Q K^T ----
            float s[8][4];
#pragma unroll
            for (int nc = 0; nc < 8; nc++)
#pragma unroll
                for (int v = 0; v < 4; v++) s[nc][v] = 0.f;
#pragma unroll
            for (int kk8 = 0; kk8 < 8; kk8++) {
                const int kk = kk8 * 8;
                uint32_t a[4];
                a[0] = __float_as_uint(qs[(wid * 16 + g    ) * LDQ + kk + tig]);
                a[1] = __float_as_uint(qs[(wid * 16 + g + 8) * LDQ + kk + tig]);
                a[2] = __float_as_uint(qs[(wid * 16 + g    ) * LDQ + kk + tig + 4]);
                a[3] = __float_as_uint(qs[(wid * 16 + g + 8) * LDQ + kk + tig + 4]);
#pragma unroll
                for (int nc = 0; nc < 8; nc++) {
                    uint32_t b[2];
                    b[0] = __float_as_uint(ks[(nc * 8 + g) * LDK + kk + tig]);
                    b[1] = __float_as_uint(ks[(nc * 8 + g) * LDK + kk + tig + 4]);
                    mma_tf32(s[nc], a, b);
                }
            }

            // ---- causal mask ----
            if (kt * 64 + 63 > wrow) {
#pragma unroll
                for (int nc = 0; nc < 8; nc++) {
                    int col = kt * 64 + nc * 8 + 2 * tig;
                    if (col     > wrow + g)     s[nc][0] = -INFINITY;
                    if (col + 1 > wrow + g)     s[nc][1] = -INFINITY;
                    if (col     > wrow + g + 8) s[nc][2] = -INFINITY;
                    if (col + 1 > wrow + g + 8) s[nc][3] = -INFINITY;
                }
            }

            // ---- warp-local online softmax (P stays in s registers) ----
            float t0 = -INFINITY, t1 = -INFINITY;
#pragma unroll
            for (int nc = 0; nc < 8; nc++) {
                t0 = fmaxf(t0, fmaxf(s[nc][0], s[nc][1]));
                t1 = fmaxf(t1, fmaxf(s[nc][2], s[nc][3]));
            }
            t0 = fmaxf(t0, __shfl_xor_sync(0xffffffffu, t0, 1));
            t0 = fmaxf(t0, __shfl_xor_sync(0xffffffffu, t0, 2));
            t1 = fmaxf(t1, __shfl_xor_sync(0xffffffffu, t1, 1));
            t1 = fmaxf(t1, __shfl_xor_sync(0xffffffffu, t1, 2));
            float mn0 = fmaxf(mrow0, t0);
            float mn1 = fmaxf(mrow1, t1);
            float sc0 = __expf(mrow0 - mn0);
            float sc1 = __expf(mrow1 - mn1);
            mrow0 = mn0; mrow1 = mn1;

            float rs0 = 0.f, rs1 = 0.f;
#pragma unroll
            for (int nc = 0; nc < 8; nc++) {
                s[nc][0] = f2tf32f(__expf(s[nc][0] - mn0));
                s[nc][1] = f2tf32f(__expf(s[nc][1] - mn0));
                s[nc][2] = f2tf32f(__expf(s[nc][2] - mn1));
                s[nc][3] = f2tf32f(__expf(s[nc][3] - mn1));
                rs0 += s[nc][0] + s[nc][1];
                rs1 += s[nc][2] + s[nc][3];
            }
            rs0 += __shfl_xor_sync(0xffffffffu, rs0, 1);
            rs0 += __shfl_xor_sync(0xffffffffu, rs0, 2);
            rs1 += __shfl_xor_sync(0xffffffffu, rs1, 1);
            rs1 += __shfl_xor_sync(0xffffffffu, rs1, 2);
            lrow0 = lrow0 * sc0 + rs0;
            lrow1 = lrow1 * sc1 + rs1;
#pragma unroll
            for (int nc = 0; nc < 8; nc++) {
                o[nc][0] *= sc0; o[nc][1] *= sc0;
                o[nc][2] *= sc1; o[nc][3] *= sc1;
            }

            // ---- O += P V (A-fragment directly from s registers) ----
#pragma unroll
            for (int j = 0; j < 8; j++) {
                uint32_t a[4];
                a[0] = __float_as_uint(s[j][0]);
                a[1] = __float_as_uint(s[j][2]);
                a[2] = __float_as_uint(s[j][1]);
                a[3] = __float_as_uint(s[j][3]);
                const int vr0 = j * 8 + 2 * tig;     // sigma(8j + tig)
#pragma unroll
                for (int nc = 0; nc < 8; nc++) {
                    uint32_t b[2];
                    b[0] = __float_as_uint(vs[(vr0    ) * LDV + nc * 8 + g]);
                    b[1] = __float_as_uint(vs[(vr0 + 1) * LDV + nc * 8 + g]);
                    mma_tf32(o[nc], a, b);
                }
            }
        }
        __syncthreads();
    }

    // normalize, tf32-round, write g_att [B,T,C]
    const int b = bh >> 4;
    const int h = bh & 15;
    const float inv0 = 1.f / lrow0;
    const float inv1 = 1.f / lrow1;
    const int t0r = wrow + g;
    const int t1r = wrow + g + 8;
#pragma unroll
    for (int nc = 0; nc < 8; nc++) {
        int d = h * DH + nc * 8 + 2 * tig;
        *(float2*)&g_att[((size_t)b * TLEN + t0r) * CDIM + d] =
            make_float2(f2tf32f(o[nc][0] * inv0), f2tf32f(o[nc][1] * inv0));
        *(float2*)&g_att[((size_t)b * TLEN + t1r) * CDIM + d] =
            make_float2(f2tf32f(o[nc][2] * inv1), f2tf32f(o[nc][3] * inv1));
    }
}

// ----------------------------------------------------------------------------
extern "C" void kernel_launch(void* const* d_in, const int* in_sizes, int n_in,
                              void* d_out, int out_size)
{
    const float* x  = (const float*)d_in[0];
    const float* Wq = (const float*)d_in[1];
    const float* Wk = (const float*)d_in[2];
    const float* Wv = (const float*)d_in[3];
    const float* Wo = (const float*)d_in[4];
    float* out = (float*)d_out;

    preround_kernel<<<dim3(4096, 5), 256>>>(x, Wq, Wk, Wv, Wo);

    cudaFuncSetAttribute(gemm_cp_kernel<1>,
                         cudaFuncAttributeMaxDynamicSharedMemorySize, GSMEM2);
    cudaFuncSetAttribute(gemm_cp_kernel<0>,
                         cudaFuncAttributeMaxDynamicSharedMemorySize, GSMEM2);

    gemm_cp_kernel<1><<<dim3(CDIM / 128, MROWS / 128, 3), 256, GSMEM2>>>(nullptr);

    cudaFuncSetAttribute(attn_mma_kernel,
                         cudaFuncAttributeMaxDynamicSharedMemorySize, ATT_SMEM);
    attn_mma_kernel<<<dim3(TLEN / QROWS, BDIM * NH), 256, ATT_SMEM>>>();

    gemm_cp_kernel<0><<<dim3(CDIM / 128, MROWS / 128, 1), 256, GSMEM2>>>(out);
}